// round 14
// baseline (speedup 1.0000x reference)
#include <cuda_runtime.h>
#include <cuda_fp16.h>
#include <math.h>
#include <cstdint>

#define NU 100000
#define NTOT 150000
#define DD 64
#define EE 1250000
#define SS 400000
#define TAU 0.2f
#define EDGE_BIAS 0.5f
#define SCAN_B 586   // ceil(NTOT/256)

typedef unsigned long long ull;

// ---- static scratch (no allocations allowed) ----
__device__ float    g_ego[NTOT * DD];      // fp32 ego
__device__ uint32_t g_ego_h[NTOT * 32];    // ego packed fp16x2
__device__ uint2    g_l1p[NTOT * 32];      // l1 paired {orig_f16x2, masked_f16x2}
__device__ uint2    g_l2p[NTOT * 32];      // l2 paired
__device__ float    g_masked[EE];
__device__ uint2    g_csr8[EE];            // {col, f16x2(val, mval)}
__device__ int      g_counts[NTOT];        // zero-init; prep++ / fill-- (self-zeroing)
__device__ int      g_rowptr[NTOT + 1];
__device__ int      g_bsum[1024];
__device__ int      g_lastS[EE];           // zero-init; atomicMax idempotent across runs
__device__ uint32_t g_w1h[64 * 64];        // W1 packed fp16x2
__device__ double   g_gate_sum;

// ================= helpers =================
__device__ __forceinline__ uint32_t smem_u32(const void* p) {
    uint32_t a;
    asm("{ .reg .u64 t; cvta.to.shared.u64 t, %1; cvt.u32.u64 %0, t; }" : "=r"(a) : "l"(p));
    return a;
}
__device__ __forceinline__ uint32_t pack_f16x2(float lo, float hi) {
    uint32_t r;
    asm("cvt.rn.f16x2.f32 %0, %1, %2;" : "=r"(r) : "f"(hi), "f"(lo));
    return r;
}
__device__ __forceinline__ float2 unpack_f16x2(uint32_t u) {
    __half2 h = *reinterpret_cast<__half2*>(&u);
    return __half22float2(h);
}
__device__ __forceinline__ void cp_async16(uint32_t dst, const void* src) {
    asm volatile("cp.async.ca.shared.global [%0], [%1], 16;"
                 :: "r"(dst), "l"(src) : "memory");
}
__device__ __forceinline__ void cp_async_wait_all() {
    asm volatile("cp.async.commit_group;" ::: "memory");
    asm volatile("cp.async.wait_group 0;" ::: "memory");
}
__device__ __forceinline__ void ldsm_x4(uint32_t (&r)[4], uint32_t addr) {
    asm volatile("ldmatrix.sync.aligned.m8n8.x4.shared.b16 {%0,%1,%2,%3}, [%4];"
        : "=r"(r[0]), "=r"(r[1]), "=r"(r[2]), "=r"(r[3]) : "r"(addr));
}
__device__ __forceinline__ void ldsm_x4t(uint32_t (&r)[4], uint32_t addr) {
    asm volatile("ldmatrix.sync.aligned.m8n8.x4.trans.shared.b16 {%0,%1,%2,%3}, [%4];"
        : "=r"(r[0]), "=r"(r[1]), "=r"(r[2]), "=r"(r[3]) : "r"(addr));
}
__device__ __forceinline__ void mma_f16(float (&c)[4], const uint32_t (&a)[4],
                                        uint32_t b0, uint32_t b1) {
    asm volatile(
        "mma.sync.aligned.m16n8k16.row.col.f32.f16.f16.f32 "
        "{%0,%1,%2,%3}, {%4,%5,%6,%7}, {%8,%9}, {%0,%1,%2,%3};"
        : "+f"(c[0]), "+f"(c[1]), "+f"(c[2]), "+f"(c[3])
        : "r"(a[0]), "r"(a[1]), "r"(a[2]), "r"(a[3]), "r"(b0), "r"(b1));
}
__device__ __forceinline__ void fma2v(float2& a, float v, float2 x) {
    a.x = fmaf(v, x.x, a.x); a.y = fmaf(v, x.y, a.y);
}

// ------------------------------------------------------------------
// 1) init: masked copy + W1 pack + gate_sum (lastS/counts self-maintaining)
// ------------------------------------------------------------------
__global__ void k_init(const float* __restrict__ vals,
                       const float* __restrict__ W1) {
    int i = blockIdx.x * blockDim.x + threadIdx.x;
    if (i < EE) g_masked[i] = vals[i];
    if (i < 4096) {
        float v0 = W1[2 * i];
        float v1 = W1[2 * i + 1];
        g_w1h[i] = pack_f16x2(v0, v1);
    }
    if (i == 0) g_gate_sum = 0.0;
}

// ------------------------------------------------------------------
// 2) combined: ego copy (fp32 + packed fp16) + degree count + lastS
// ------------------------------------------------------------------
__global__ void k_prep(const float* __restrict__ user,
                       const float* __restrict__ item,
                       const int* __restrict__ rows,
                       const int* __restrict__ sidx) {
    int i = blockIdx.x * blockDim.x + threadIdx.x;
    if (i < NTOT * 32) {
        int j = 2 * i;
        float v0 = (j < NU * DD) ? user[j] : item[j - NU * DD];
        float v1 = (j + 1 < NU * DD) ? user[j + 1] : item[j + 1 - NU * DD];
        g_ego[j] = v0;
        g_ego[j + 1] = v1;
        g_ego_h[i] = pack_f16x2(v0, v1);
    }
    if (i < EE) atomicAdd(&g_counts[rows[i]], 1);
    if (i < SS) atomicMax(&g_lastS[sidx[i]], i);
}

// ------------------------------------------------------------------
// 3) gate MLP: fp16 mma.sync, 128 threads/block, M=32 edges per warp
// ------------------------------------------------------------------
#define TE 128
#define A_STRIDE 136
#define B_STRIDE 72
#define A_TILE_B (128 * A_STRIDE * 2)
#define B_TILE_B (128 * B_STRIDE * 2)
#define GATE_DYN (A_TILE_B + B_TILE_B)

__global__ void __launch_bounds__(128)
k_gate_mma(const int* __restrict__ rows, const int* __restrict__ cols,
           const float* __restrict__ vals, const int* __restrict__ sidx,
           const float* __restrict__ eps,
           const float* __restrict__ b1,
           const float* __restrict__ W2, const float* __restrict__ b2) {
    extern __shared__ char dsm[];
    const uint32_t A0 = smem_u32(dsm);
    const uint32_t B0 = A0 + A_TILE_B;

    __shared__ float  b1s[64], W2s[64];
    __shared__ int    eidx[TE];
    __shared__ double gpart[4];

    const int tid  = threadIdx.x;
    const int wid  = tid >> 5;
    const int lane = tid & 31;
    const int base = blockIdx.x * TE;

    if (tid < 64) { b1s[tid] = b1[tid]; W2s[tid] = W2[tid]; }

    // ---- stage B via cp.async: 1024 x 16B over 128 threads ----
    {
        const uint4* src = (const uint4*)g_w1h;
        for (int i = tid; i < 1024; i += 128) {
            int k = i >> 3, c4 = (i & 7) * 4;
            cp_async16(B0 + (uint32_t)(k * B_STRIDE + 2 * c4) * 2u, src + i);
        }
    }
    // ---- stage A via cp.async: 1 thread/edge, 16 x 16B ----
    {
        int e = tid;
        int s = base + e;
        int idx = __ldg(&sidx[s]);
        eidx[e] = idx;
        int n0 = __ldg(&rows[idx]);
        int n1 = __ldg(&cols[idx]);
        const uint4* s0p = (const uint4*)(g_ego_h + n0 * 32);
        const uint4* s1p = (const uint4*)(g_ego_h + n1 * 32);
        uint32_t ro = A0 + (uint32_t)(e * A_STRIDE) * 2u;
#pragma unroll
        for (int j = 0; j < 8; j++) cp_async16(ro + (uint32_t)j * 16u, s0p + j);
#pragma unroll
        for (int j = 0; j < 8; j++) cp_async16(ro + 128u + (uint32_t)j * 16u, s1p + j);
    }
    cp_async_wait_all();
    __syncthreads();

    // ---- mainloop: warp covers 32 edges (2 m16 tiles), 8 k-steps ----
    float C[2][8][4];
#pragma unroll
    for (int m = 0; m < 2; m++)
#pragma unroll
        for (int n = 0; n < 8; n++)
#pragma unroll
            for (int q = 0; q < 4; q++) C[m][n][q] = 0.f;

    const uint32_t a_off0 =
        (uint32_t)((wid * 32 + (lane & 15)) * A_STRIDE + (lane >> 4) * 8) * 2u;
    const uint32_t a_off1 = a_off0 + (uint32_t)(16 * A_STRIDE) * 2u;
    const int bg  = lane >> 3;
    const int br  = lane & 7;
    const int b_krow_off = (bg & 1) * 8 + br;
    const int b_ncol_off = (bg >> 1) * 8;

#pragma unroll
    for (int k = 0; k < 8; k++) {
        uint32_t a0[4], a1[4];
        ldsm_x4(a0, A0 + a_off0 + (uint32_t)(k * 32));
        ldsm_x4(a1, A0 + a_off1 + (uint32_t)(k * 32));
        uint32_t b_base = B0 +
            (uint32_t)((k * 16 + b_krow_off) * B_STRIDE + b_ncol_off) * 2u;
#pragma unroll
        for (int nb = 0; nb < 4; nb++) {
            uint32_t b[4];
            ldsm_x4t(b, b_base + (uint32_t)(nb * 32));
            mma_f16(C[0][2 * nb],     a0, b[0], b[1]);
            mma_f16(C[0][2 * nb + 1], a0, b[2], b[3]);
            mma_f16(C[1][2 * nb],     a1, b[0], b[1]);
            mma_f16(C[1][2 * nb + 1], a1, b[2], b[3]);
        }
    }

    // ---- epilogue ----
    const int qr = lane >> 2;
    const int qc = (lane & 3) * 2;
    float pl[2], ph[2];
#pragma unroll
    for (int m = 0; m < 2; m++) {
        float a = 0.f, b = 0.f;
#pragma unroll
        for (int n = 0; n < 8; n++) {
            int c0 = n * 8 + qc, c1 = c0 + 1;
            a += fmaxf(C[m][n][0] + b1s[c0], 0.f) * W2s[c0]
               + fmaxf(C[m][n][1] + b1s[c1], 0.f) * W2s[c1];
            b += fmaxf(C[m][n][2] + b1s[c0], 0.f) * W2s[c0]
               + fmaxf(C[m][n][3] + b1s[c1], 0.f) * W2s[c1];
        }
        a += __shfl_xor_sync(0xffffffffu, a, 1);
        a += __shfl_xor_sync(0xffffffffu, a, 2);
        b += __shfl_xor_sync(0xffffffffu, b, 1);
        b += __shfl_xor_sync(0xffffffffu, b, 2);
        pl[m] = a; ph[m] = b;
    }

    double gsum = 0.0;
    if ((lane & 3) == 0) {
        float b2v = __ldg(b2);
#pragma unroll
        for (int m = 0; m < 2; m++) {
#pragma unroll
            for (int h = 0; h < 2; h++) {
                int e = wid * 32 + m * 16 + h * 8 + qr;
                int s = base + e;
                float logit = (h ? ph[m] : pl[m]) + b2v;
                float ee = __ldg(&eps[s]) * (1.f - 2e-6f) + 1e-6f;
                float gumbel = logf(ee) - log1pf(-ee);
                float gate = 1.f / (1.f + expf(-(logit + gumbel) / TAU)) + EDGE_BIAS;
                gsum += (double)gate;
                int idx = eidx[e];
                if (g_lastS[idx] == s) g_masked[idx] = vals[idx] * gate;
            }
        }
    }
#pragma unroll
    for (int off = 16; off; off >>= 1)
        gsum += __shfl_xor_sync(0xffffffffu, gsum, off);
    if (lane == 0) gpart[wid] = gsum;
    __syncthreads();
    if (tid == 0)
        atomicAdd(&g_gate_sum, gpart[0] + gpart[1] + gpart[2] + gpart[3]);
}

// ------------------------------------------------------------------
// 4) CSR scan (3-phase) + fill (atomicSub slot; counts self-zeroing)
// ------------------------------------------------------------------
__global__ void k_scan1() {
    __shared__ int sh[256];
    int i = blockIdx.x * 256 + threadIdx.x;
    int v = (i < NTOT) ? g_counts[i] : 0;
    sh[threadIdx.x] = v;
    __syncthreads();
    for (int off = 128; off; off >>= 1) {
        if (threadIdx.x < off) sh[threadIdx.x] += sh[threadIdx.x + off];
        __syncthreads();
    }
    if (threadIdx.x == 0) g_bsum[blockIdx.x] = sh[0];
}

__global__ void k_scan2() {
    __shared__ int sh[1024];
    int t = threadIdx.x;
    int v = (t < SCAN_B) ? g_bsum[t] : 0;
    sh[t] = v;
    __syncthreads();
    for (int off = 1; off < 1024; off <<= 1) {
        int u = (t >= off) ? sh[t - off] : 0;
        __syncthreads();
        sh[t] += u;
        __syncthreads();
    }
    if (t < SCAN_B) g_bsum[t] = sh[t] - v;  // exclusive
}

__global__ void k_scan3() {
    __shared__ int sh[256];
    int i = blockIdx.x * 256 + threadIdx.x;
    int v = (i < NTOT) ? g_counts[i] : 0;
    sh[threadIdx.x] = v;
    __syncthreads();
    for (int off = 1; off < 256; off <<= 1) {
        int u = (threadIdx.x >= off) ? sh[threadIdx.x - off] : 0;
        __syncthreads();
        sh[threadIdx.x] += u;
        __syncthreads();
    }
    if (i < NTOT) g_rowptr[i] = g_bsum[blockIdx.x] + sh[threadIdx.x] - v;
    if (i == 0) g_rowptr[NTOT] = EE;
}

__global__ void k_fill(const int* __restrict__ rows, const int* __restrict__ cols,
                       const float* __restrict__ vals) {
    int e = blockIdx.x * blockDim.x + threadIdx.x;
    if (e >= EE) return;
    int r = rows[e];
    int old = atomicSub(&g_counts[r], 1);
    int slot = g_rowptr[r] + old - 1;
    uint2 rec;
    rec.x = (uint32_t)cols[e];
    rec.y = pack_f16x2(vals[e], g_masked[e]);
    g_csr8[slot] = rec;
}

// ------------------------------------------------------------------
// 5) SPMM layer 1: fp16 ego gather -> paired fp16 l1
// ------------------------------------------------------------------
__global__ void k_spmm_l1() {
    int warp = (blockIdx.x * blockDim.x + threadIdx.x) >> 5;
    int lane = threadIdx.x & 31;
    if (warp >= NTOT) return;
    int s0 = __ldg(&g_rowptr[warp]);
    int s1 = __ldg(&g_rowptr[warp + 1]);
    float2 aa = make_float2(0.f, 0.f), ab = make_float2(0.f, 0.f);
    int s = s0;
    for (; s + 4 <= s1; s += 4) {
        uint2 r0 = __ldcs(&g_csr8[s]),     r1 = __ldcs(&g_csr8[s + 1]);
        uint2 r2 = __ldcs(&g_csr8[s + 2]), r3 = __ldcs(&g_csr8[s + 3]);
        float2 v0 = unpack_f16x2(r0.y), v1 = unpack_f16x2(r1.y);
        float2 v2 = unpack_f16x2(r2.y), v3 = unpack_f16x2(r3.y);
        float2 x0 = unpack_f16x2(__ldg(&g_ego_h[r0.x * 32 + lane]));
        float2 x1 = unpack_f16x2(__ldg(&g_ego_h[r1.x * 32 + lane]));
        float2 x2 = unpack_f16x2(__ldg(&g_ego_h[r2.x * 32 + lane]));
        float2 x3 = unpack_f16x2(__ldg(&g_ego_h[r3.x * 32 + lane]));
        fma2v(aa, v0.x, x0); fma2v(ab, v0.y, x0);
        fma2v(aa, v1.x, x1); fma2v(ab, v1.y, x1);
        fma2v(aa, v2.x, x2); fma2v(ab, v2.y, x2);
        fma2v(aa, v3.x, x3); fma2v(ab, v3.y, x3);
    }
    for (; s < s1; s++) {
        uint2 r = __ldcs(&g_csr8[s]);
        float2 v = unpack_f16x2(r.y);
        float2 x = unpack_f16x2(__ldg(&g_ego_h[r.x * 32 + lane]));
        fma2v(aa, v.x, x); fma2v(ab, v.y, x);
    }
    __stcs(&g_l1p[warp * 32 + lane],
           make_uint2(pack_f16x2(aa.x, aa.y), pack_f16x2(ab.x, ab.y)));
}

// ------------------------------------------------------------------
// 6) SPMM layer 2: paired fp16 l1 gather -> paired fp16 l2
// ------------------------------------------------------------------
__global__ void k_spmm_l2() {
    int warp = (blockIdx.x * blockDim.x + threadIdx.x) >> 5;
    int lane = threadIdx.x & 31;
    if (warp >= NTOT) return;
    int s0 = __ldg(&g_rowptr[warp]);
    int s1 = __ldg(&g_rowptr[warp + 1]);
    float2 aa = make_float2(0.f, 0.f), ab = make_float2(0.f, 0.f);
    int s = s0;
    for (; s + 4 <= s1; s += 4) {
        uint2 r0 = __ldcs(&g_csr8[s]),     r1 = __ldcs(&g_csr8[s + 1]);
        uint2 r2 = __ldcs(&g_csr8[s + 2]), r3 = __ldcs(&g_csr8[s + 3]);
        float2 v0 = unpack_f16x2(r0.y), v1 = unpack_f16x2(r1.y);
        float2 v2 = unpack_f16x2(r2.y), v3 = unpack_f16x2(r3.y);
        uint2 u0 = __ldg(&g_l1p[r0.x * 32 + lane]);
        uint2 u1 = __ldg(&g_l1p[r1.x * 32 + lane]);
        uint2 u2 = __ldg(&g_l1p[r2.x * 32 + lane]);
        uint2 u3 = __ldg(&g_l1p[r3.x * 32 + lane]);
        fma2v(aa, v0.x, unpack_f16x2(u0.x)); fma2v(ab, v0.y, unpack_f16x2(u0.y));
        fma2v(aa, v1.x, unpack_f16x2(u1.x)); fma2v(ab, v1.y, unpack_f16x2(u1.y));
        fma2v(aa, v2.x, unpack_f16x2(u2.x)); fma2v(ab, v2.y, unpack_f16x2(u2.y));
        fma2v(aa, v3.x, unpack_f16x2(u3.x)); fma2v(ab, v3.y, unpack_f16x2(u3.y));
    }
    for (; s < s1; s++) {
        uint2 r = __ldcs(&g_csr8[s]);
        float2 v = unpack_f16x2(r.y);
        uint2 u = __ldg(&g_l1p[r.x * 32 + lane]);
        fma2v(aa, v.x, unpack_f16x2(u.x)); fma2v(ab, v.y, unpack_f16x2(u.y));
    }
    __stcs(&g_l2p[warp * 32 + lane],
           make_uint2(pack_f16x2(aa.x, aa.y), pack_f16x2(ab.x, ab.y)));
}

// ------------------------------------------------------------------
// 7) SPMM layer 3: paired fp16 l2 gather + fused mean
// ------------------------------------------------------------------
__global__ void k_spmm_l3(float* __restrict__ out) {
    int warp = (blockIdx.x * blockDim.x + threadIdx.x) >> 5;
    int lane = threadIdx.x & 31;
    if (warp >= NTOT) return;
    int s0 = __ldg(&g_rowptr[warp]);
    int s1 = __ldg(&g_rowptr[warp + 1]);
    float2 aa = make_float2(0.f, 0.f), ab = make_float2(0.f, 0.f);
    int s = s0;
    for (; s + 4 <= s1; s += 4) {
        uint2 r0 = __ldcs(&g_csr8[s]),     r1 = __ldcs(&g_csr8[s + 1]);
        uint2 r2 = __ldcs(&g_csr8[s + 2]), r3 = __ldcs(&g_csr8[s + 3]);
        float2 v0 = unpack_f16x2(r0.y), v1 = unpack_f16x2(r1.y);
        float2 v2 = unpack_f16x2(r2.y), v3 = unpack_f16x2(r3.y);
        uint2 u0 = __ldg(&g_l2p[r0.x * 32 + lane]);
        uint2 u1 = __ldg(&g_l2p[r1.x * 32 + lane]);
        uint2 u2 = __ldg(&g_l2p[r2.x * 32 + lane]);
        uint2 u3 = __ldg(&g_l2p[r3.x * 32 + lane]);
        fma2v(aa, v0.x, unpack_f16x2(u0.x)); fma2v(ab, v0.y, unpack_f16x2(u0.y));
        fma2v(aa, v1.x, unpack_f16x2(u1.x)); fma2v(ab, v1.y, unpack_f16x2(u1.y));
        fma2v(aa, v2.x, unpack_f16x2(u2.x)); fma2v(ab, v2.y, unpack_f16x2(u2.y));
        fma2v(aa, v3.x, unpack_f16x2(u3.x)); fma2v(ab, v3.y, unpack_f16x2(u3.y));
    }
    for (; s < s1; s++) {
        uint2 r = __ldcs(&g_csr8[s]);
        float2 v = unpack_f16x2(r.y);
        uint2 u = __ldg(&g_l2p[r.x * 32 + lane]);
        fma2v(aa, v.x, unpack_f16x2(u.x)); fma2v(ab, v.y, unpack_f16x2(u.y));
    }
    const float2* E = (const float2*)g_ego;
    float2 e  = E[warp * 32 + lane];
    uint2 u1 = __ldg(&g_l1p[warp * 32 + lane]);
    uint2 u2 = __ldg(&g_l2p[warp * 32 + lane]);
    float2 p1 = unpack_f16x2(u1.x), q1 = unpack_f16x2(u1.y);
    float2 p2 = unpack_f16x2(u2.x), q2 = unpack_f16x2(u2.y);
    float2* outA = (float2*)out;
    float2* outB = (float2*)out + NTOT * 32;
    __stcs(&outA[warp * 32 + lane],
           make_float2((e.x + p1.x + p2.x + aa.x) * 0.25f,
                       (e.y + p1.y + p2.y + aa.y) * 0.25f));
    __stcs(&outB[warp * 32 + lane],
           make_float2((e.x + q1.x + q2.x + ab.x) * 0.25f,
                       (e.y + q1.y + q2.y + ab.y) * 0.25f));
}

// ------------------------------------------------------------------
// 8) gate mean
// ------------------------------------------------------------------
__global__ void k_final(float* __restrict__ out) {
    out[2 * NTOT * DD] = (float)(g_gate_sum / (double)SS);
}

extern "C" void kernel_launch(void* const* d_in, const int* in_sizes, int n_in,
                              void* d_out, int out_size) {
    const float* user = (const float*)d_in[0];
    const float* item = (const float*)d_in[1];
    const int*   rows = (const int*)d_in[2];
    const int*   cols = (const int*)d_in[3];
    const float* vals = (const float*)d_in[4];
    const int*   sidx = (const int*)d_in[5];
    const float* eps  = (const float*)d_in[6];
    const float* W1   = (const float*)d_in[7];
    const float* b1   = (const float*)d_in[8];
    const float* W2   = (const float*)d_in[9];
    const float* b2   = (const float*)d_in[10];
    float* out = (float*)d_out;

    static int smem_set = 0;
    if (!smem_set) {
        cudaFuncSetAttribute(k_gate_mma,
                             cudaFuncAttributeMaxDynamicSharedMemorySize, GATE_DYN);
        smem_set = 1;
    }

    const int TB = 256;
    k_init<<<(EE + TB - 1) / TB, TB>>>(vals, W1);
    k_prep<<<(NTOT * DD + TB - 1) / TB, TB>>>(user, item, rows, sidx);
    k_scan1<<<SCAN_B, 256>>>();
    k_gate_mma<<<SS / TE, 128, GATE_DYN>>>(rows, cols, vals, sidx, eps, b1, W2, b2);
    k_scan2<<<1, 1024>>>();
    k_scan3<<<SCAN_B, 256>>>();
    k_fill<<<(EE + TB - 1) / TB, TB>>>(rows, cols, vals);

    const int SPMM_BLOCKS = (NTOT * 32 + TB - 1) / TB;
    k_spmm_l1<<<SPMM_BLOCKS, TB>>>();
    k_spmm_l2<<<SPMM_BLOCKS, TB>>>();
    k_spmm_l3<<<SPMM_BLOCKS, TB>>>(out);

    k_final<<<1, 1>>>(out);
}

// round 15
// speedup vs baseline: 1.0602x; 1.0602x over previous
#include <cuda_runtime.h>
#include <cuda_fp16.h>
#include <math.h>
#include <cstdint>

#define NU 100000
#define NTOT 150000
#define DD 64
#define EE 1250000
#define SS 400000
#define TAU 0.2f
#define EDGE_BIAS 0.5f
#define SCAN_B 586   // ceil(NTOT/256)

typedef unsigned long long ull;

// ---- static scratch (no allocations allowed) ----
__device__ float    g_ego[NTOT * DD];      // fp32 ego
__device__ uint32_t g_ego_h[NTOT * 32];    // ego packed fp16x2
__device__ uint2    g_l1p[NTOT * 32];      // l1 paired {orig_f16x2, masked_f16x2}
__device__ uint2    g_l2p[NTOT * 32];      // l2 paired
__device__ float    g_masked[EE];
__device__ uint2    g_csr8[EE];            // {col, f16x2(val, mval)}
__device__ int      g_counts[NTOT];        // zero-init; prep++ / fill-- (self-zeroing)
__device__ int      g_rowptr[NTOT + 1];
__device__ int      g_bsum[1024];
__device__ int      g_lastS[EE];           // zero-init; atomicMax idempotent across runs
__device__ uint32_t g_w1h[64 * 64];        // W1 packed fp16x2
__device__ double   g_gate_sum;

// ================= helpers =================
__device__ __forceinline__ uint32_t smem_u32(const void* p) {
    uint32_t a;
    asm("{ .reg .u64 t; cvta.to.shared.u64 t, %1; cvt.u32.u64 %0, t; }" : "=r"(a) : "l"(p));
    return a;
}
__device__ __forceinline__ uint32_t pack_f16x2(float lo, float hi) {
    uint32_t r;
    asm("cvt.rn.f16x2.f32 %0, %1, %2;" : "=r"(r) : "f"(hi), "f"(lo));
    return r;
}
__device__ __forceinline__ float2 unpack_f16x2(uint32_t u) {
    __half2 h = *reinterpret_cast<__half2*>(&u);
    return __half22float2(h);
}
__device__ __forceinline__ void cp_async16(uint32_t dst, const void* src) {
    asm volatile("cp.async.ca.shared.global [%0], [%1], 16;"
                 :: "r"(dst), "l"(src) : "memory");
}
__device__ __forceinline__ void cp_async_wait_all() {
    asm volatile("cp.async.commit_group;" ::: "memory");
    asm volatile("cp.async.wait_group 0;" ::: "memory");
}
__device__ __forceinline__ void ldsm_x4(uint32_t (&r)[4], uint32_t addr) {
    asm volatile("ldmatrix.sync.aligned.m8n8.x4.shared.b16 {%0,%1,%2,%3}, [%4];"
        : "=r"(r[0]), "=r"(r[1]), "=r"(r[2]), "=r"(r[3]) : "r"(addr));
}
__device__ __forceinline__ void ldsm_x4t(uint32_t (&r)[4], uint32_t addr) {
    asm volatile("ldmatrix.sync.aligned.m8n8.x4.trans.shared.b16 {%0,%1,%2,%3}, [%4];"
        : "=r"(r[0]), "=r"(r[1]), "=r"(r[2]), "=r"(r[3]) : "r"(addr));
}
__device__ __forceinline__ void mma_f16(float (&c)[4], const uint32_t (&a)[4],
                                        uint32_t b0, uint32_t b1) {
    asm volatile(
        "mma.sync.aligned.m16n8k16.row.col.f32.f16.f16.f32 "
        "{%0,%1,%2,%3}, {%4,%5,%6,%7}, {%8,%9}, {%0,%1,%2,%3};"
        : "+f"(c[0]), "+f"(c[1]), "+f"(c[2]), "+f"(c[3])
        : "r"(a[0]), "r"(a[1]), "r"(a[2]), "r"(a[3]), "r"(b0), "r"(b1));
}
__device__ __forceinline__ void fma2v(float2& a, float v, float2 x) {
    a.x = fmaf(v, x.x, a.x); a.y = fmaf(v, x.y, a.y);
}

// ------------------------------------------------------------------
// 1) combined prep: ego copy + masked copy + W1 pack + count + lastS
// ------------------------------------------------------------------
__global__ void k_prep(const float* __restrict__ user,
                       const float* __restrict__ item,
                       const float* __restrict__ vals,
                       const float* __restrict__ W1,
                       const int* __restrict__ rows,
                       const int* __restrict__ sidx) {
    int i = blockIdx.x * blockDim.x + threadIdx.x;
    if (i < NTOT * 32) {
        int j = 2 * i;
        float v0 = (j < NU * DD) ? user[j] : item[j - NU * DD];
        float v1 = (j + 1 < NU * DD) ? user[j + 1] : item[j + 1 - NU * DD];
        g_ego[j] = v0;
        g_ego[j + 1] = v1;
        g_ego_h[i] = pack_f16x2(v0, v1);
    }
    if (i < EE) {
        g_masked[i] = vals[i];
        atomicAdd(&g_counts[rows[i]], 1);
    }
    if (i < SS) atomicMax(&g_lastS[sidx[i]], i);
    if (i < 4096) {
        float v0 = W1[2 * i];
        float v1 = W1[2 * i + 1];
        g_w1h[i] = pack_f16x2(v0, v1);
    }
    if (i == 0) g_gate_sum = 0.0;
}

// ------------------------------------------------------------------
// 2) gate MLP: fp16 mma.sync, cp.async staging (R13 proven, 76us)
// ------------------------------------------------------------------
#define TE 128
#define A_STRIDE 136
#define B_STRIDE 72
#define A_TILE_B (128 * A_STRIDE * 2)
#define B_TILE_B (128 * B_STRIDE * 2)
#define GATE_DYN (A_TILE_B + B_TILE_B)

__global__ void __launch_bounds__(256)
k_gate_mma(const int* __restrict__ rows, const int* __restrict__ cols,
           const float* __restrict__ vals, const int* __restrict__ sidx,
           const float* __restrict__ eps,
           const float* __restrict__ b1,
           const float* __restrict__ W2, const float* __restrict__ b2) {
    extern __shared__ char dsm[];
    const uint32_t A0 = smem_u32(dsm);
    const uint32_t B0 = A0 + A_TILE_B;

    __shared__ float  b1s[64], W2s[64];
    __shared__ int    eidx[TE];
    __shared__ double gpart[8];

    const int tid  = threadIdx.x;
    const int wid  = tid >> 5;
    const int lane = tid & 31;
    const int base = blockIdx.x * TE;

    if (tid < 64) { b1s[tid] = b1[tid]; W2s[tid] = W2[tid]; }

    // ---- stage B via cp.async: 1024 x 16B ----
    {
        const uint4* src = (const uint4*)g_w1h;
        for (int i = tid; i < 1024; i += 256) {
            int k = i >> 3, c4 = (i & 7) * 4;
            cp_async16(B0 + (uint32_t)(k * B_STRIDE + 2 * c4) * 2u, src + i);
        }
    }
    // ---- stage A via cp.async: 2 threads/edge, 8 x 16B each ----
    {
        int e = tid >> 1, p = tid & 1;
        int s = base + e;
        int idx = __ldg(&sidx[s]);
        if (p == 0) eidx[e] = idx;
        int node = p ? __ldg(&cols[idx]) : __ldg(&rows[idx]);
        const uint4* src = (const uint4*)(g_ego_h + node * 32);
        uint32_t rowoff = A0 + (uint32_t)(e * A_STRIDE + p * DD) * 2u;
#pragma unroll
        for (int j = 0; j < 8; j++)
            cp_async16(rowoff + (uint32_t)j * 16u, src + j);
    }
    cp_async_wait_all();
    __syncthreads();

    float C[8][4];
#pragma unroll
    for (int n = 0; n < 8; n++)
#pragma unroll
        for (int q = 0; q < 4; q++) C[n][q] = 0.f;

    const uint32_t a_lane_off =
        (uint32_t)((wid * 16 + (lane & 15)) * A_STRIDE + (lane >> 4) * 8) * 2u;
    const int bg  = lane >> 3;
    const int br  = lane & 7;
    const int b_krow_off = (bg & 1) * 8 + br;
    const int b_ncol_off = (bg >> 1) * 8;

#pragma unroll
    for (int k = 0; k < 8; k++) {
        uint32_t a[4];
        ldsm_x4(a, A0 + a_lane_off + (uint32_t)(k * 16 * 2));
        uint32_t b_base = B0 +
            (uint32_t)((k * 16 + b_krow_off) * B_STRIDE + b_ncol_off) * 2u;
#pragma unroll
        for (int nb = 0; nb < 4; nb++) {
            uint32_t b[4];
            ldsm_x4t(b, b_base + (uint32_t)(nb * 16 * 2));
            mma_f16(C[2 * nb],     a, b[0], b[1]);
            mma_f16(C[2 * nb + 1], a, b[2], b[3]);
        }
    }

    const int qr = lane >> 2;
    const int qc = (lane & 3) * 2;
    float pl = 0.f, ph = 0.f;
#pragma unroll
    for (int n = 0; n < 8; n++) {
        int c0 = n * 8 + qc, c1 = c0 + 1;
        pl += fmaxf(C[n][0] + b1s[c0], 0.f) * W2s[c0]
            + fmaxf(C[n][1] + b1s[c1], 0.f) * W2s[c1];
        ph += fmaxf(C[n][2] + b1s[c0], 0.f) * W2s[c0]
            + fmaxf(C[n][3] + b1s[c1], 0.f) * W2s[c1];
    }
    pl += __shfl_xor_sync(0xffffffffu, pl, 1);
    pl += __shfl_xor_sync(0xffffffffu, pl, 2);
    ph += __shfl_xor_sync(0xffffffffu, ph, 1);
    ph += __shfl_xor_sync(0xffffffffu, ph, 2);

    double gsum = 0.0;
    if ((lane & 3) == 0) {
        float b2v = __ldg(b2);
        float logit[2] = {pl + b2v, ph + b2v};
#pragma unroll
        for (int h = 0; h < 2; h++) {
            int e = wid * 16 + qr + h * 8;
            int s = base + e;
            float ee = __ldg(&eps[s]) * (1.f - 2e-6f) + 1e-6f;
            float gumbel = logf(ee) - log1pf(-ee);
            float gate = 1.f / (1.f + expf(-(logit[h] + gumbel) / TAU)) + EDGE_BIAS;
            gsum += (double)gate;
            int idx = eidx[e];
            if (g_lastS[idx] == s) g_masked[idx] = vals[idx] * gate;
        }
    }
#pragma unroll
    for (int off = 16; off; off >>= 1)
        gsum += __shfl_xor_sync(0xffffffffu, gsum, off);
    if (lane == 0) gpart[wid] = gsum;
    __syncthreads();
    if (tid == 0) {
        double t = 0.0;
#pragma unroll
        for (int i = 0; i < 8; i++) t += gpart[i];
        atomicAdd(&g_gate_sum, t);
    }
}

// ------------------------------------------------------------------
// 3) CSR scan (3-phase) + fill (atomicSub slot; counts self-zeroing)
// ------------------------------------------------------------------
__global__ void k_scan1() {
    __shared__ int sh[256];
    int i = blockIdx.x * 256 + threadIdx.x;
    int v = (i < NTOT) ? g_counts[i] : 0;
    sh[threadIdx.x] = v;
    __syncthreads();
    for (int off = 128; off; off >>= 1) {
        if (threadIdx.x < off) sh[threadIdx.x] += sh[threadIdx.x + off];
        __syncthreads();
    }
    if (threadIdx.x == 0) g_bsum[blockIdx.x] = sh[0];
}

__global__ void k_scan2() {
    __shared__ int sh[1024];
    int t = threadIdx.x;
    int v = (t < SCAN_B) ? g_bsum[t] : 0;
    sh[t] = v;
    __syncthreads();
    for (int off = 1; off < 1024; off <<= 1) {
        int u = (t >= off) ? sh[t - off] : 0;
        __syncthreads();
        sh[t] += u;
        __syncthreads();
    }
    if (t < SCAN_B) g_bsum[t] = sh[t] - v;  // exclusive
}

__global__ void k_scan3() {
    __shared__ int sh[256];
    int i = blockIdx.x * 256 + threadIdx.x;
    int v = (i < NTOT) ? g_counts[i] : 0;
    sh[threadIdx.x] = v;
    __syncthreads();
    for (int off = 1; off < 256; off <<= 1) {
        int u = (threadIdx.x >= off) ? sh[threadIdx.x - off] : 0;
        __syncthreads();
        sh[threadIdx.x] += u;
        __syncthreads();
    }
    if (i < NTOT) g_rowptr[i] = g_bsum[blockIdx.x] + sh[threadIdx.x] - v;
    if (i == 0) g_rowptr[NTOT] = EE;
}

__global__ void k_fill(const int* __restrict__ rows, const int* __restrict__ cols,
                       const float* __restrict__ vals) {
    int e = blockIdx.x * blockDim.x + threadIdx.x;
    if (e >= EE) return;
    int r = rows[e];
    int old = atomicSub(&g_counts[r], 1);
    int slot = g_rowptr[r] + old - 1;
    uint2 rec;
    rec.x = (uint32_t)cols[e];
    rec.y = pack_f16x2(vals[e], g_masked[e]);
    g_csr8[slot] = rec;
}

// ------------------------------------------------------------------
// 4) SPMM layer 1: fp16 ego gather -> paired fp16 l1
// ------------------------------------------------------------------
__global__ void k_spmm_l1() {
    int warp = (blockIdx.x * blockDim.x + threadIdx.x) >> 5;
    int lane = threadIdx.x & 31;
    if (warp >= NTOT) return;
    int s0 = __ldg(&g_rowptr[warp]);
    int s1 = __ldg(&g_rowptr[warp + 1]);
    float2 aa = make_float2(0.f, 0.f), ab = make_float2(0.f, 0.f);
    int s = s0;
    for (; s + 4 <= s1; s += 4) {
        uint2 r0 = __ldcs(&g_csr8[s]),     r1 = __ldcs(&g_csr8[s + 1]);
        uint2 r2 = __ldcs(&g_csr8[s + 2]), r3 = __ldcs(&g_csr8[s + 3]);
        float2 v0 = unpack_f16x2(r0.y), v1 = unpack_f16x2(r1.y);
        float2 v2 = unpack_f16x2(r2.y), v3 = unpack_f16x2(r3.y);
        float2 x0 = unpack_f16x2(__ldg(&g_ego_h[r0.x * 32 + lane]));
        float2 x1 = unpack_f16x2(__ldg(&g_ego_h[r1.x * 32 + lane]));
        float2 x2 = unpack_f16x2(__ldg(&g_ego_h[r2.x * 32 + lane]));
        float2 x3 = unpack_f16x2(__ldg(&g_ego_h[r3.x * 32 + lane]));
        fma2v(aa, v0.x, x0); fma2v(ab, v0.y, x0);
        fma2v(aa, v1.x, x1); fma2v(ab, v1.y, x1);
        fma2v(aa, v2.x, x2); fma2v(ab, v2.y, x2);
        fma2v(aa, v3.x, x3); fma2v(ab, v3.y, x3);
    }
    for (; s < s1; s++) {
        uint2 r = __ldcs(&g_csr8[s]);
        float2 v = unpack_f16x2(r.y);
        float2 x = unpack_f16x2(__ldg(&g_ego_h[r.x * 32 + lane]));
        fma2v(aa, v.x, x); fma2v(ab, v.y, x);
    }
    __stcs(&g_l1p[warp * 32 + lane],
           make_uint2(pack_f16x2(aa.x, aa.y), pack_f16x2(ab.x, ab.y)));
}

// ------------------------------------------------------------------
// 5) SPMM layer 2: paired fp16 l1 gather -> paired fp16 l2
// ------------------------------------------------------------------
__global__ void k_spmm_l2() {
    int warp = (blockIdx.x * blockDim.x + threadIdx.x) >> 5;
    int lane = threadIdx.x & 31;
    if (warp >= NTOT) return;
    int s0 = __ldg(&g_rowptr[warp]);
    int s1 = __ldg(&g_rowptr[warp + 1]);
    float2 aa = make_float2(0.f, 0.f), ab = make_float2(0.f, 0.f);
    int s = s0;
    for (; s + 4 <= s1; s += 4) {
        uint2 r0 = __ldcs(&g_csr8[s]),     r1 = __ldcs(&g_csr8[s + 1]);
        uint2 r2 = __ldcs(&g_csr8[s + 2]), r3 = __ldcs(&g_csr8[s + 3]);
        float2 v0 = unpack_f16x2(r0.y), v1 = unpack_f16x2(r1.y);
        float2 v2 = unpack_f16x2(r2.y), v3 = unpack_f16x2(r3.y);
        uint2 u0 = __ldg(&g_l1p[r0.x * 32 + lane]);
        uint2 u1 = __ldg(&g_l1p[r1.x * 32 + lane]);
        uint2 u2 = __ldg(&g_l1p[r2.x * 32 + lane]);
        uint2 u3 = __ldg(&g_l1p[r3.x * 32 + lane]);
        fma2v(aa, v0.x, unpack_f16x2(u0.x)); fma2v(ab, v0.y, unpack_f16x2(u0.y));
        fma2v(aa, v1.x, unpack_f16x2(u1.x)); fma2v(ab, v1.y, unpack_f16x2(u1.y));
        fma2v(aa, v2.x, unpack_f16x2(u2.x)); fma2v(ab, v2.y, unpack_f16x2(u2.y));
        fma2v(aa, v3.x, unpack_f16x2(u3.x)); fma2v(ab, v3.y, unpack_f16x2(u3.y));
    }
    for (; s < s1; s++) {
        uint2 r = __ldcs(&g_csr8[s]);
        float2 v = unpack_f16x2(r.y);
        uint2 u = __ldg(&g_l1p[r.x * 32 + lane]);
        fma2v(aa, v.x, unpack_f16x2(u.x)); fma2v(ab, v.y, unpack_f16x2(u.y));
    }
    __stcs(&g_l2p[warp * 32 + lane],
           make_uint2(pack_f16x2(aa.x, aa.y), pack_f16x2(ab.x, ab.y)));
}

// ------------------------------------------------------------------
// 6) SPMM layer 3: paired fp16 l2 gather + fused mean
// ------------------------------------------------------------------
__global__ void k_spmm_l3(float* __restrict__ out) {
    int warp = (blockIdx.x * blockDim.x + threadIdx.x) >> 5;
    int lane = threadIdx.x & 31;
    if (warp >= NTOT) return;
    int s0 = __ldg(&g_rowptr[warp]);
    int s1 = __ldg(&g_rowptr[warp + 1]);
    float2 aa = make_float2(0.f, 0.f), ab = make_float2(0.f, 0.f);
    int s = s0;
    for (; s + 4 <= s1; s += 4) {
        uint2 r0 = __ldcs(&g_csr8[s]),     r1 = __ldcs(&g_csr8[s + 1]);
        uint2 r2 = __ldcs(&g_csr8[s + 2]), r3 = __ldcs(&g_csr8[s + 3]);
        float2 v0 = unpack_f16x2(r0.y), v1 = unpack_f16x2(r1.y);
        float2 v2 = unpack_f16x2(r2.y), v3 = unpack_f16x2(r3.y);
        uint2 u0 = __ldg(&g_l2p[r0.x * 32 + lane]);
        uint2 u1 = __ldg(&g_l2p[r1.x * 32 + lane]);
        uint2 u2 = __ldg(&g_l2p[r2.x * 32 + lane]);
        uint2 u3 = __ldg(&g_l2p[r3.x * 32 + lane]);
        fma2v(aa, v0.x, unpack_f16x2(u0.x)); fma2v(ab, v0.y, unpack_f16x2(u0.y));
        fma2v(aa, v1.x, unpack_f16x2(u1.x)); fma2v(ab, v1.y, unpack_f16x2(u1.y));
        fma2v(aa, v2.x, unpack_f16x2(u2.x)); fma2v(ab, v2.y, unpack_f16x2(u2.y));
        fma2v(aa, v3.x, unpack_f16x2(u3.x)); fma2v(ab, v3.y, unpack_f16x2(u3.y));
    }
    for (; s < s1; s++) {
        uint2 r = __ldcs(&g_csr8[s]);
        float2 v = unpack_f16x2(r.y);
        uint2 u = __ldg(&g_l2p[r.x * 32 + lane]);
        fma2v(aa, v.x, unpack_f16x2(u.x)); fma2v(ab, v.y, unpack_f16x2(u.y));
    }
    const float2* E = (const float2*)g_ego;
    float2 e  = E[warp * 32 + lane];
    uint2 u1 = __ldg(&g_l1p[warp * 32 + lane]);
    uint2 u2 = __ldg(&g_l2p[warp * 32 + lane]);
    float2 p1 = unpack_f16x2(u1.x), q1 = unpack_f16x2(u1.y);
    float2 p2 = unpack_f16x2(u2.x), q2 = unpack_f16x2(u2.y);
    float2* outA = (float2*)out;
    float2* outB = (float2*)out + NTOT * 32;
    __stcs(&outA[warp * 32 + lane],
           make_float2((e.x + p1.x + p2.x + aa.x) * 0.25f,
                       (e.y + p1.y + p2.y + aa.y) * 0.25f));
    __stcs(&outB[warp * 32 + lane],
           make_float2((e.x + q1.x + q2.x + ab.x) * 0.25f,
                       (e.y + q1.y + q2.y + ab.y) * 0.25f));
}

// ------------------------------------------------------------------
// 7) gate mean
// ------------------------------------------------------------------
__global__ void k_final(float* __restrict__ out) {
    out[2 * NTOT * DD] = (float)(g_gate_sum / (double)SS);
}

extern "C" void kernel_launch(void* const* d_in, const int* in_sizes, int n_in,
                              void* d_out, int out_size) {
    const float* user = (const float*)d_in[0];
    const float* item = (const float*)d_in[1];
    const int*   rows = (const int*)d_in[2];
    const int*   cols = (const int*)d_in[3];
    const float* vals = (const float*)d_in[4];
    const int*   sidx = (const int*)d_in[5];
    const float* eps  = (const float*)d_in[6];
    const float* W1   = (const float*)d_in[7];
    const float* b1   = (const float*)d_in[8];
    const float* W2   = (const float*)d_in[9];
    const float* b2   = (const float*)d_in[10];
    float* out = (float*)d_out;

    static int smem_set = 0;
    if (!smem_set) {
        cudaFuncSetAttribute(k_gate_mma,
                             cudaFuncAttributeMaxDynamicSharedMemorySize, GATE_DYN);
        smem_set = 1;
    }

    const int TB = 256;
    k_prep<<<(NTOT * DD / 2 + TB - 1) / TB, TB>>>(user, item, vals, W1, rows, sidx);
    k_scan1<<<SCAN_B, 256>>>();
    k_gate_mma<<<SS / TE, 256, GATE_DYN>>>(rows, cols, vals, sidx, eps, b1, W2, b2);
    k_scan2<<<1, 1024>>>();
    k_scan3<<<SCAN_B, 256>>>();
    k_fill<<<(EE + TB - 1) / TB, TB>>>(rows, cols, vals);

    const int SPMM_BLOCKS = (NTOT * 32 + TB - 1) / TB;
    k_spmm_l1<<<SPMM_BLOCKS, TB>>>();
    k_spmm_l2<<<SPMM_BLOCKS, TB>>>();
    k_spmm_l3<<<SPMM_BLOCKS, TB>>>(out);

    k_final<<<1, 1>>>(out);
}